// round 12
// baseline (speedup 1.0000x reference)
#include <cuda_runtime.h>
#include <cstdint>
#include <mma.h>
#include <math.h>
#include <cuda_fp16.h>

using namespace nvcuda;

#define T_TOK 2048
#define H_DIM 2048
#define IM_DIM 1024
#define IS_DIM 2048
#define NE 16
#define TOPK 8
#define RSCALE 2.5f

// ---------------- scratch (__device__ globals: allocation-free) ----------------
__device__ int    g_counts[NE];
__device__ int    g_tok[NE * T_TOK];
__device__ float  g_wt[NE * T_TOK];
__device__ int    g_slotoff[T_TOK * TOPK];

__device__ __half hH[(size_t)T_TOK * H_DIM];
__device__ __half WgH[(size_t)NE * H_DIM * IM_DIM];
__device__ __half WuH[(size_t)NE * H_DIM * IM_DIM];
__device__ __half WdH[(size_t)NE * IM_DIM * H_DIM];
__device__ __half sWgH[(size_t)H_DIM * IS_DIM];
__device__ __half sWuH[(size_t)H_DIM * IS_DIM];
__device__ __half sWdH[(size_t)IS_DIM * H_DIM];
__device__ __half g_actH[(size_t)NE * T_TOK * IM_DIM];   // weighted silu(g)*u (routed)
__device__ __half g_act_sH[(size_t)T_TOK * IS_DIM];      // shared silu(g)*u
__device__ float  g_eo[(size_t)NE * T_TOK * H_DIM];      // routed weighted expert outputs

// ---------------- cp.async helpers ----------------
__device__ __forceinline__ void cp16(void* sdst, const void* gsrc, bool valid) {
    unsigned int sa = (unsigned int)__cvta_generic_to_shared(sdst);
    int sz = valid ? 16 : 0;
    asm volatile("cp.async.cg.shared.global [%0], [%1], 16, %2;\n" :: "r"(sa), "l"(gsrc), "r"(sz));
}
#define CP_COMMIT asm volatile("cp.async.commit_group;\n" ::: "memory")
#define CP_WAIT1  asm volatile("cp.async.wait_group 1;\n" ::: "memory")
#define CP_WAIT0  asm volatile("cp.async.wait_group 0;\n" ::: "memory")

// ---------------- fp32 -> fp16 conversion ----------------
__global__ void __launch_bounds__(256) f2h_kernel(
    const float4* __restrict__ src, __half* __restrict__ dst, size_t n4)
{
    size_t i = (size_t)blockIdx.x * blockDim.x + threadIdx.x;
    if (i >= n4) return;
    float4 v = src[i];
    __half2 p0 = __floats2half2_rn(v.x, v.y);
    __half2 p1 = __floats2half2_rn(v.z, v.w);
    uint2 u;
    u.x = reinterpret_cast<unsigned&>(p0);
    u.y = reinterpret_cast<unsigned&>(p1);
    *reinterpret_cast<uint2*>(dst + 4 * i) = u;
}

// ---------------- router ----------------
__global__ void zero_counts_kernel() {
    if (threadIdx.x < NE) g_counts[threadIdx.x] = 0;
}

__global__ void __launch_bounds__(256) router_kernel(
    const float* __restrict__ hmat, const float* __restrict__ gate_w)
{
    int t = blockIdx.x * 8 + (threadIdx.x >> 5);
    int lane = threadIdx.x & 31;
    if (t >= T_TOK) return;
    const float4* hr = (const float4*)(hmat + (size_t)t * H_DIM);

    float4 hv[16];
    #pragma unroll
    for (int i = 0; i < 16; i++) hv[i] = hr[lane + i * 32];

    float logits[NE];
    #pragma unroll
    for (int e = 0; e < NE; e++) {
        const float4* gw = (const float4*)(gate_w + e * H_DIM);
        float s = 0.f;
        #pragma unroll
        for (int i = 0; i < 16; i++) {
            float4 g = gw[lane + i * 32];
            s += hv[i].x * g.x + hv[i].y * g.y + hv[i].z * g.z + hv[i].w * g.w;
        }
        #pragma unroll
        for (int o = 16; o > 0; o >>= 1) s += __shfl_down_sync(0xffffffff, s, o);
        logits[e] = __shfl_sync(0xffffffff, s, 0);
    }

    if (lane == 0) {
        float w[NE]; bool sel[NE];
        #pragma unroll
        for (int e = 0; e < NE; e++) { w[e] = 1.f / (1.f + expf(-logits[e])); sel[e] = false; }
        int idx[TOPK]; float sum = 0.f;
        #pragma unroll
        for (int r = 0; r < TOPK; r++) {
            int bi = -1; float bv = -1e30f;
            #pragma unroll
            for (int e = 0; e < NE; e++)
                if (!sel[e] && w[e] > bv) { bv = w[e]; bi = e; }
            sel[bi] = true; idx[r] = bi; sum += bv;
        }
        float inv = RSCALE / (sum + 1e-6f);
        #pragma unroll
        for (int r = 0; r < TOPK; r++) {
            int e = idx[r];
            int slot = atomicAdd(&g_counts[e], 1);
            g_tok[e * T_TOK + slot] = t;
            g_wt[e * T_TOK + slot]  = w[e] * inv;
            g_slotoff[t * TOPK + r] = e * T_TOK + slot;
        }
    }
}

// ---------------- fused gate+up+SiLU GEMM (fp16 wmma, 3-stage cp.async pipeline) ----------------
// C tile 128x64; 256 thr = 8 warps (4 M x 2 N), each warp 32x32 per matrix. K-step 32.
// Routing weight applied in epilogue (distributes over the down GEMM).
#define GU_STG (128*40 + 2*32*72)                      // 9728 halves per stage
#define GU_SMEM_BYTES (3 * GU_STG * 2)                 // 58368; covers 128x68 f32 epilogue (34816)

template<bool SH, int NCOLS>
__global__ void __launch_bounds__(256, 2) gateup_kernel()
{
    extern __shared__ __align__(16) char dynraw[];
    const int e    = SH ? 0 : blockIdx.z;
    const int M    = SH ? T_TOK : g_counts[e];
    const int row0 = blockIdx.y * 128;
    if (row0 >= M) return;
    const int col0 = blockIdx.x * 64;

    const __half* Wg = SH ? sWgH : WgH + (size_t)e * H_DIM * NCOLS;
    const __half* Wu = SH ? sWuH : WuH + (size_t)e * H_DIM * NCOLS;
    __half* actOut   = SH ? g_act_sH : g_actH + (size_t)e * T_TOK * IM_DIM;

    __shared__ int   sTok[128];
    __shared__ float sW[128];
    const int tid = threadIdx.x;
    if (tid < 128) {
        int r = row0 + tid;
        if (r < M) { sTok[tid] = SH ? r : g_tok[e * T_TOK + r]; sW[tid] = SH ? 1.f : g_wt[e * T_TOK + r]; }
        else       { sTok[tid] = -1; sW[tid] = 0.f; }
    }
    __syncthreads();

    auto load_tiles = [&](int buf, int ks) {
        __half* sA = (__half*)dynraw + buf * GU_STG;
        __half* sB = sA + 128 * 40;
        const int k0 = ks * 32;
        #pragma unroll
        for (int i = 0; i < 2; i++) {                 // A: 128 rows x 32 halves = 512 cp16
            int f = tid + i * 256;
            int r = f >> 2, c4 = f & 3;
            int t = sTok[r];
            cp16(sA + r * 40 + c4 * 8,
                 hH + (size_t)(t < 0 ? 0 : t) * H_DIM + k0 + c4 * 8, t >= 0);
        }
        #pragma unroll
        for (int i = 0; i < 2; i++) {                 // B: 2 x 32 x 64 halves = 512 cp16
            int f = tid + i * 256;
            int m = f >> 8, rem = f & 255;
            int r = rem >> 3, c8 = rem & 7;
            const __half* W = m ? Wu : Wg;
            cp16(sB + m * (32 * 72) + r * 72 + c8 * 8,
                 W + (size_t)(k0 + r) * NCOLS + col0 + c8 * 8, true);
        }
    };

    const int warp = tid >> 5;
    const int wm = warp & 3, wn = warp >> 2;

    wmma::fragment<wmma::accumulator, 16, 16, 16, float> accg[2][2], accu[2][2];
    #pragma unroll
    for (int i = 0; i < 2; i++)
        #pragma unroll
        for (int j = 0; j < 2; j++) { wmma::fill_fragment(accg[i][j], 0.f); wmma::fill_fragment(accu[i][j], 0.f); }

    const int NK = H_DIM / 32;
    load_tiles(0, 0); CP_COMMIT;
    load_tiles(1, 1); CP_COMMIT;

    int buf = 0;
    for (int ks = 0; ks < NK; ks++) {
        if (ks + 1 < NK) { CP_WAIT1; } else { CP_WAIT0; }
        __syncthreads();
        if (ks + 2 < NK) {
            int nb = buf + 2; if (nb >= 3) nb -= 3;
            load_tiles(nb, ks + 2); CP_COMMIT;
        }

        __half* sA = (__half*)dynraw + buf * GU_STG;
        __half* sB = sA + 128 * 40;
        #pragma unroll
        for (int kk = 0; kk < 2; kk++) {
            wmma::fragment<wmma::matrix_a, 16, 16, 16, __half, wmma::row_major> a[2];
            #pragma unroll
            for (int i = 0; i < 2; i++)
                wmma::load_matrix_sync(a[i], sA + (wm * 32 + i * 16) * 40 + kk * 16, 40);
            #pragma unroll
            for (int j = 0; j < 2; j++) {
                wmma::fragment<wmma::matrix_b, 16, 16, 16, __half, wmma::row_major> b;
                wmma::load_matrix_sync(b, sB + (kk * 16) * 72 + wn * 32 + j * 16, 72);
                #pragma unroll
                for (int i = 0; i < 2; i++) wmma::mma_sync(accg[i][j], a[i], b, accg[i][j]);
                wmma::load_matrix_sync(b, sB + 32 * 72 + (kk * 16) * 72 + wn * 32 + j * 16, 72);
                #pragma unroll
                for (int i = 0; i < 2; i++) wmma::mma_sync(accu[i][j], a[i], b, accu[i][j]);
            }
        }
        if (++buf == 3) buf = 0;
    }
    __syncthreads();

    // SiLU(g)*u in registers, park fp32 tile in smem, scale by routing weight, store half2
    float* sC = (float*)dynraw;                        // 128 x 68 fp32
    #pragma unroll
    for (int i = 0; i < 2; i++)
        #pragma unroll
        for (int j = 0; j < 2; j++) {
            #pragma unroll
            for (int x = 0; x < accg[i][j].num_elements; x++) {
                float g = accg[i][j].x[x];
                accg[i][j].x[x] = (g / (1.f + expf(-g))) * accu[i][j].x[x];
            }
            wmma::store_matrix_sync(sC + (wm * 32 + i * 16) * 68 + wn * 32 + j * 16, accg[i][j], 68, wmma::mem_row_major);
        }
    __syncthreads();

    #pragma unroll
    for (int it = 0; it < 16; it++) {                  // 128 x 32 half2
        int li = tid + it * 256;
        int r = li >> 5, c2 = li & 31;
        float wt = sW[r];
        __half2 v = __floats2half2_rn(sC[r * 68 + c2 * 2] * wt, sC[r * 68 + c2 * 2 + 1] * wt);
        *reinterpret_cast<__half2*>(actOut + (size_t)(row0 + r) * NCOLS + col0 + c2 * 2) = v;
    }
}

// ---------------- down GEMM (128x128 tile, 3-stage pipeline, direct global store) ----------------
// 8 warps (4 M x 2 N), each warp 32x64 output. K-step 32.
#define DN_STG (128*40 + 32*136)                       // 9472 halves per stage
#define DN_SMEM_BYTES (3 * DN_STG * 2)                 // 56832

template<bool SH, int KDIM>
__global__ void __launch_bounds__(256, 2) down_kernel(float* __restrict__ outp)
{
    extern __shared__ __align__(16) char dynraw[];
    const int e    = SH ? 0 : blockIdx.z;
    const int M    = SH ? T_TOK : g_counts[e];
    const int row0 = blockIdx.y * 128;
    if (row0 >= M) return;
    const int col0 = blockIdx.x * 128;

    const __half* A = SH ? g_act_sH : g_actH + (size_t)e * T_TOK * IM_DIM;
    const __half* B = SH ? sWdH : WdH + (size_t)e * KDIM * H_DIM;
    float* dstBase  = SH ? outp : g_eo + (size_t)e * T_TOK * H_DIM;

    const int tid = threadIdx.x;

    auto load_tiles = [&](int buf, int ks) {
        __half* sA = (__half*)dynraw + buf * DN_STG;
        __half* sB = sA + 128 * 40;
        const int k0 = ks * 32;
        #pragma unroll
        for (int i = 0; i < 2; i++) {                 // A: 128 x 32 halves = 512 cp16
            int f = tid + i * 256;
            int r = f >> 2, c4 = f & 3;
            bool v = (row0 + r) < M;
            cp16(sA + r * 40 + c4 * 8,
                 A + (size_t)(v ? row0 + r : 0) * KDIM + k0 + c4 * 8, v);
        }
        #pragma unroll
        for (int i = 0; i < 2; i++) {                 // B: 32 x 128 halves = 512 cp16
            int f = tid + i * 256;
            int r = f >> 4, c8 = f & 15;
            cp16(sB + r * 136 + c8 * 8,
                 B + (size_t)(k0 + r) * H_DIM + col0 + c8 * 8, true);
        }
    };

    const int warp = tid >> 5;
    const int wm = warp & 3, wn = warp >> 2;

    wmma::fragment<wmma::accumulator, 16, 16, 16, float> acc[2][4];
    #pragma unroll
    for (int i = 0; i < 2; i++)
        #pragma unroll
        for (int j = 0; j < 4; j++) wmma::fill_fragment(acc[i][j], 0.f);

    const int NK = KDIM / 32;
    load_tiles(0, 0); CP_COMMIT;
    load_tiles(1, 1); CP_COMMIT;

    int buf = 0;
    for (int ks = 0; ks < NK; ks++) {
        if (ks + 1 < NK) { CP_WAIT1; } else { CP_WAIT0; }
        __syncthreads();
        if (ks + 2 < NK) {
            int nb = buf + 2; if (nb >= 3) nb -= 3;
            load_tiles(nb, ks + 2); CP_COMMIT;
        }

        __half* sA = (__half*)dynraw + buf * DN_STG;
        __half* sB = sA + 128 * 40;
        #pragma unroll
        for (int kk = 0; kk < 2; kk++) {
            wmma::fragment<wmma::matrix_a, 16, 16, 16, __half, wmma::row_major> a[2];
            #pragma unroll
            for (int i = 0; i < 2; i++)
                wmma::load_matrix_sync(a[i], sA + (wm * 32 + i * 16) * 40 + kk * 16, 40);
            #pragma unroll
            for (int j = 0; j < 4; j++) {
                wmma::fragment<wmma::matrix_b, 16, 16, 16, __half, wmma::row_major> b;
                wmma::load_matrix_sync(b, sB + (kk * 16) * 136 + wn * 64 + j * 16, 136);
                #pragma unroll
                for (int i = 0; i < 2; i++) wmma::mma_sync(acc[i][j], a[i], b, acc[i][j]);
            }
        }
        if (++buf == 3) buf = 0;
    }

    // direct global store (weight already folded into activations)
    #pragma unroll
    for (int i = 0; i < 2; i++)
        #pragma unroll
        for (int j = 0; j < 4; j++) {
            float* dst = dstBase + (size_t)(row0 + wm * 32 + i * 16) * H_DIM + col0 + wn * 64 + j * 16;
            wmma::store_matrix_sync(dst, acc[i][j], H_DIM, wmma::mem_row_major);
        }
}

// ---------------- combine: out += sum of 8 routed slots per token ----------------
__global__ void __launch_bounds__(256) combine_kernel(float* __restrict__ out)
{
    int idx = blockIdx.x * 256 + threadIdx.x;            // over T*H/4
    int t = idx >> 9;                                    // H/4 = 512
    int c = idx & 511;
    const int* so = g_slotoff + t * TOPK;
    float4 acc = reinterpret_cast<float4*>(out)[idx];
    #pragma unroll
    for (int r = 0; r < TOPK; r++) {
        float4 v = reinterpret_cast<const float4*>(g_eo + (size_t)so[r] * H_DIM)[c];
        acc.x += v.x; acc.y += v.y; acc.z += v.z; acc.w += v.w;
    }
    reinterpret_cast<float4*>(out)[idx] = acc;
}

// ---------------- launch ----------------
static void launch_f2h(const float* src, void* dstSym, size_t n) {
    size_t n4 = n / 4;
    f2h_kernel<<<(unsigned)((n4 + 255) / 256), 256>>>((const float4*)src, (__half*)dstSym, n4);
}

extern "C" void kernel_launch(void* const* d_in, const int* in_sizes, int n_in,
                              void* d_out, int out_size)
{
    const float* h   = (const float*)d_in[0];
    const float* gw  = (const float*)d_in[1];
    const float* Wg  = (const float*)d_in[2];
    const float* Wu  = (const float*)d_in[3];
    const float* Wd  = (const float*)d_in[4];
    const float* sWg = (const float*)d_in[5];
    const float* sWu = (const float*)d_in[6];
    const float* sWd = (const float*)d_in[7];
    float* out = (float*)d_out;

    void *p_h, *p_wg, *p_wu, *p_wd, *p_swg, *p_swu, *p_swd;
    cudaGetSymbolAddress(&p_h,   hH);
    cudaGetSymbolAddress(&p_wg,  WgH);
    cudaGetSymbolAddress(&p_wu,  WuH);
    cudaGetSymbolAddress(&p_wd,  WdH);
    cudaGetSymbolAddress(&p_swg, sWgH);
    cudaGetSymbolAddress(&p_swu, sWuH);
    cudaGetSymbolAddress(&p_swd, sWdH);

    cudaFuncSetAttribute(gateup_kernel<true,  IS_DIM>, cudaFuncAttributeMaxDynamicSharedMemorySize, GU_SMEM_BYTES);
    cudaFuncSetAttribute(gateup_kernel<false, IM_DIM>, cudaFuncAttributeMaxDynamicSharedMemorySize, GU_SMEM_BYTES);
    cudaFuncSetAttribute(down_kernel<true,  IS_DIM>,   cudaFuncAttributeMaxDynamicSharedMemorySize, DN_SMEM_BYTES);
    cudaFuncSetAttribute(down_kernel<false, IM_DIM>,   cudaFuncAttributeMaxDynamicSharedMemorySize, DN_SMEM_BYTES);

    // fp32 -> fp16 conversions
    launch_f2h(h,   p_h,   (size_t)T_TOK * H_DIM);
    launch_f2h(Wg,  p_wg,  (size_t)NE * H_DIM * IM_DIM);
    launch_f2h(Wu,  p_wu,  (size_t)NE * H_DIM * IM_DIM);
    launch_f2h(Wd,  p_wd,  (size_t)NE * IM_DIM * H_DIM);
    launch_f2h(sWg, p_swg, (size_t)H_DIM * IS_DIM);
    launch_f2h(sWu, p_swu, (size_t)H_DIM * IS_DIM);
    launch_f2h(sWd, p_swd, (size_t)IS_DIM * H_DIM);

    zero_counts_kernel<<<1, 32>>>();
    router_kernel<<<T_TOK / 8, 256>>>(h, gw);

    gateup_kernel<true,  IS_DIM><<<dim3(IS_DIM / 64, T_TOK / 128, 1),  256, GU_SMEM_BYTES>>>();
    gateup_kernel<false, IM_DIM><<<dim3(IM_DIM / 64, T_TOK / 128, NE), 256, GU_SMEM_BYTES>>>();

    down_kernel<true,  IS_DIM><<<dim3(H_DIM / 128, T_TOK / 128, 1),  256, DN_SMEM_BYTES>>>(out);
    down_kernel<false, IM_DIM><<<dim3(H_DIM / 128, T_TOK / 128, NE), 256, DN_SMEM_BYTES>>>(out);

    combine_kernel<<<(T_TOK * H_DIM / 4) / 256, 256>>>(out);
}

// round 13
// speedup vs baseline: 1.0957x; 1.0957x over previous
#include <cuda_runtime.h>
#include <cstdint>
#include <mma.h>
#include <math.h>
#include <cuda_fp16.h>

using namespace nvcuda;

#define T_TOK 2048
#define H_DIM 2048
#define IM_DIM 1024
#define IS_DIM 2048
#define NE 16
#define TOPK 8
#define RSCALE 2.5f

// ---------------- scratch (__device__ globals: allocation-free) ----------------
__device__ int    g_counts[NE];
__device__ int    g_tok[NE * T_TOK];
__device__ float  g_wt[NE * T_TOK];
__device__ int    g_slotoff[T_TOK * TOPK];

__device__ __half hH[(size_t)T_TOK * H_DIM];
__device__ __half WgH[(size_t)NE * H_DIM * IM_DIM];
__device__ __half WuH[(size_t)NE * H_DIM * IM_DIM];
__device__ __half WdH[(size_t)NE * IM_DIM * H_DIM];
__device__ __half sWgH[(size_t)H_DIM * IS_DIM];
__device__ __half sWuH[(size_t)H_DIM * IS_DIM];
__device__ __half sWdH[(size_t)IS_DIM * H_DIM];
__device__ __half g_actH[(size_t)NE * T_TOK * IM_DIM];   // weighted silu(g)*u (routed)
__device__ __half g_act_sH[(size_t)T_TOK * IS_DIM];      // shared silu(g)*u
__device__ float  g_eo[(size_t)NE * T_TOK * H_DIM];      // routed weighted expert outputs

// ---------------- cp.async helpers ----------------
__device__ __forceinline__ void cp16(void* sdst, const void* gsrc, bool valid) {
    unsigned int sa = (unsigned int)__cvta_generic_to_shared(sdst);
    int sz = valid ? 16 : 0;
    asm volatile("cp.async.cg.shared.global [%0], [%1], 16, %2;\n" :: "r"(sa), "l"(gsrc), "r"(sz));
}
#define CP_COMMIT asm volatile("cp.async.commit_group;\n" ::: "memory")
#define CP_WAIT1  asm volatile("cp.async.wait_group 1;\n" ::: "memory")
#define CP_WAIT0  asm volatile("cp.async.wait_group 0;\n" ::: "memory")

// ---------------- fp32 -> fp16 conversion ----------------
__global__ void __launch_bounds__(256) f2h_kernel(
    const float4* __restrict__ src, __half* __restrict__ dst, size_t n4)
{
    size_t i = (size_t)blockIdx.x * blockDim.x + threadIdx.x;
    if (i >= n4) return;
    float4 v = src[i];
    __half2 p0 = __floats2half2_rn(v.x, v.y);
    __half2 p1 = __floats2half2_rn(v.z, v.w);
    uint2 u;
    u.x = reinterpret_cast<unsigned&>(p0);
    u.y = reinterpret_cast<unsigned&>(p1);
    *reinterpret_cast<uint2*>(dst + 4 * i) = u;
}

// ---------------- router ----------------
__global__ void zero_counts_kernel() {
    if (threadIdx.x < NE) g_counts[threadIdx.x] = 0;
}

__global__ void __launch_bounds__(256) router_kernel(
    const float* __restrict__ hmat, const float* __restrict__ gate_w)
{
    int t = blockIdx.x * 8 + (threadIdx.x >> 5);
    int lane = threadIdx.x & 31;
    if (t >= T_TOK) return;
    const float4* hr = (const float4*)(hmat + (size_t)t * H_DIM);

    float4 hv[16];
    #pragma unroll
    for (int i = 0; i < 16; i++) hv[i] = hr[lane + i * 32];

    float logits[NE];
    #pragma unroll
    for (int e = 0; e < NE; e++) {
        const float4* gw = (const float4*)(gate_w + e * H_DIM);
        float s = 0.f;
        #pragma unroll
        for (int i = 0; i < 16; i++) {
            float4 g = gw[lane + i * 32];
            s += hv[i].x * g.x + hv[i].y * g.y + hv[i].z * g.z + hv[i].w * g.w;
        }
        #pragma unroll
        for (int o = 16; o > 0; o >>= 1) s += __shfl_down_sync(0xffffffff, s, o);
        logits[e] = __shfl_sync(0xffffffff, s, 0);
    }

    if (lane == 0) {
        float w[NE]; bool sel[NE];
        #pragma unroll
        for (int e = 0; e < NE; e++) { w[e] = 1.f / (1.f + expf(-logits[e])); sel[e] = false; }
        int idx[TOPK]; float sum = 0.f;
        #pragma unroll
        for (int r = 0; r < TOPK; r++) {
            int bi = -1; float bv = -1e30f;
            #pragma unroll
            for (int e = 0; e < NE; e++)
                if (!sel[e] && w[e] > bv) { bv = w[e]; bi = e; }
            sel[bi] = true; idx[r] = bi; sum += bv;
        }
        float inv = RSCALE / (sum + 1e-6f);
        #pragma unroll
        for (int r = 0; r < TOPK; r++) {
            int e = idx[r];
            int slot = atomicAdd(&g_counts[e], 1);
            g_tok[e * T_TOK + slot] = t;
            g_wt[e * T_TOK + slot]  = w[e] * inv;
            g_slotoff[t * TOPK + r] = e * T_TOK + slot;
        }
    }
}

// ---------------- merged gate+up+SiLU GEMM (fp16 wmma, 2-stage cp.async, R10 schedule) ----------------
// blockIdx.z in [0,NE]: z<NE -> routed expert z (NCOLS=IM), z==NE -> shared (NCOLS=IS).
// C tile 128x64; 256 thr = 8 warps (4 M x 2 N), each warp 32x32 per matrix. K-step 32.
// Routing weight applied in epilogue (distributes over the down GEMM).
#define GU_STG (128*40 + 2*32*72)
#define GU_SMEM_BYTES (2 * GU_STG * 2)          // 38912; also covers 128x68 f32 epilogue (34816)

__global__ void __launch_bounds__(256, 2) gateup_kernel()
{
    extern __shared__ __align__(16) char dynraw[];
    const bool SH   = (blockIdx.z == NE);
    const int e     = SH ? 0 : blockIdx.z;
    const int ncols = SH ? IS_DIM : IM_DIM;
    const int col0  = blockIdx.x * 64;
    if (col0 >= ncols) return;
    const int M    = SH ? T_TOK : g_counts[e];
    const int row0 = blockIdx.y * 128;
    if (row0 >= M) return;

    const __half* Wg = SH ? sWgH : WgH + (size_t)e * H_DIM * IM_DIM;
    const __half* Wu = SH ? sWuH : WuH + (size_t)e * H_DIM * IM_DIM;
    __half* actOut   = SH ? g_act_sH : g_actH + (size_t)e * T_TOK * IM_DIM;

    __shared__ int   sTok[128];
    __shared__ float sW[128];
    const int tid = threadIdx.x;
    if (tid < 128) {
        int r = row0 + tid;
        if (r < M) { sTok[tid] = SH ? r : g_tok[e * T_TOK + r]; sW[tid] = SH ? 1.f : g_wt[e * T_TOK + r]; }
        else       { sTok[tid] = -1; sW[tid] = 0.f; }
    }
    __syncthreads();

    auto load_tiles = [&](int buf, int ks) {
        __half* sA = (__half*)dynraw + buf * GU_STG;
        __half* sB = sA + 128 * 40;
        const int k0 = ks * 32;
        #pragma unroll
        for (int i = 0; i < 2; i++) {                 // A: 128 rows x 32 halves = 512 cp16
            int f = tid + i * 256;
            int r = f >> 2, c4 = f & 3;
            int t = sTok[r];
            cp16(sA + r * 40 + c4 * 8,
                 hH + (size_t)(t < 0 ? 0 : t) * H_DIM + k0 + c4 * 8, t >= 0);
        }
        #pragma unroll
        for (int i = 0; i < 2; i++) {                 // B: 2 x 32 x 64 halves = 512 cp16
            int f = tid + i * 256;
            int m = f >> 8, rem = f & 255;
            int r = rem >> 3, c8 = rem & 7;
            const __half* W = m ? Wu : Wg;
            cp16(sB + m * (32 * 72) + r * 72 + c8 * 8,
                 W + (size_t)(k0 + r) * ncols + col0 + c8 * 8, true);
        }
    };

    const int warp = tid >> 5;
    const int wm = warp & 3, wn = warp >> 2;

    wmma::fragment<wmma::accumulator, 16, 16, 16, float> accg[2][2], accu[2][2];
    #pragma unroll
    for (int i = 0; i < 2; i++)
        #pragma unroll
        for (int j = 0; j < 2; j++) { wmma::fill_fragment(accg[i][j], 0.f); wmma::fill_fragment(accu[i][j], 0.f); }

    const int NK = H_DIM / 32;
    load_tiles(0, 0); CP_COMMIT;

    for (int ks = 0; ks < NK; ks++) {
        if (ks + 1 < NK) { load_tiles((ks + 1) & 1, ks + 1); CP_COMMIT; CP_WAIT1; }
        else             { CP_WAIT0; }
        __syncthreads();

        __half* sA = (__half*)dynraw + (ks & 1) * GU_STG;
        __half* sB = sA + 128 * 40;
        #pragma unroll
        for (int kk = 0; kk < 2; kk++) {
            wmma::fragment<wmma::matrix_a, 16, 16, 16, __half, wmma::row_major> a[2];
            #pragma unroll
            for (int i = 0; i < 2; i++)
                wmma::load_matrix_sync(a[i], sA + (wm * 32 + i * 16) * 40 + kk * 16, 40);
            #pragma unroll
            for (int j = 0; j < 2; j++) {
                wmma::fragment<wmma::matrix_b, 16, 16, 16, __half, wmma::row_major> b;
                wmma::load_matrix_sync(b, sB + (kk * 16) * 72 + wn * 32 + j * 16, 72);
                #pragma unroll
                for (int i = 0; i < 2; i++) wmma::mma_sync(accg[i][j], a[i], b, accg[i][j]);
                wmma::load_matrix_sync(b, sB + 32 * 72 + (kk * 16) * 72 + wn * 32 + j * 16, 72);
                #pragma unroll
                for (int i = 0; i < 2; i++) wmma::mma_sync(accu[i][j], a[i], b, accu[i][j]);
            }
        }
        __syncthreads();
    }

    // SiLU(g)*u in registers, park fp32 tile in smem, scale by routing weight, store half2
    float* sC = (float*)dynraw;                        // 128 x 68 fp32
    #pragma unroll
    for (int i = 0; i < 2; i++)
        #pragma unroll
        for (int j = 0; j < 2; j++) {
            #pragma unroll
            for (int x = 0; x < accg[i][j].num_elements; x++) {
                float g = accg[i][j].x[x];
                accg[i][j].x[x] = (g / (1.f + expf(-g))) * accu[i][j].x[x];
            }
            wmma::store_matrix_sync(sC + (wm * 32 + i * 16) * 68 + wn * 32 + j * 16, accg[i][j], 68, wmma::mem_row_major);
        }
    __syncthreads();

    #pragma unroll
    for (int it = 0; it < 16; it++) {                  // 128 x 32 half2
        int li = tid + it * 256;
        int r = li >> 5, c2 = li & 31;
        float wt = sW[r];
        __half2 v = __floats2half2_rn(sC[r * 68 + c2 * 2] * wt, sC[r * 68 + c2 * 2 + 1] * wt);
        *reinterpret_cast<__half2*>(actOut + (size_t)(row0 + r) * ncols + col0 + c2 * 2) = v;
    }
}

// ---------------- merged down GEMM (128x128 tile, direct global store, no atomics) ----------------
// blockIdx.z in [0,NE]: z<NE -> routed expert z (KDIM=IM, dst=g_eo), z==NE -> shared (KDIM=IS, dst=out).
// 8 warps (4 M x 2 N), each warp 32x64 output. K-step 32.
#define DN_STG (128*40 + 32*136)                       // 9472 halves
#define DN_SMEM_BYTES (2 * DN_STG * 2)                 // 37888

__global__ void __launch_bounds__(256, 2) down_kernel(float* __restrict__ outp)
{
    extern __shared__ __align__(16) char dynraw[];
    const bool SH  = (blockIdx.z == NE);
    const int e    = SH ? 0 : blockIdx.z;
    const int kdim = SH ? IS_DIM : IM_DIM;
    const int M    = SH ? T_TOK : g_counts[e];
    const int row0 = blockIdx.y * 128;
    if (row0 >= M) return;
    const int col0 = blockIdx.x * 128;

    const __half* A = SH ? g_act_sH : g_actH + (size_t)e * T_TOK * IM_DIM;
    const __half* B = SH ? sWdH : WdH + (size_t)e * IM_DIM * H_DIM;
    float* dstBase  = SH ? outp : g_eo + (size_t)e * T_TOK * H_DIM;

    const int tid = threadIdx.x;

    auto load_tiles = [&](int buf, int ks) {
        __half* sA = (__half*)dynraw + buf * DN_STG;
        __half* sB = sA + 128 * 40;
        const int k0 = ks * 32;
        #pragma unroll
        for (int i = 0; i < 2; i++) {                 // A: 128 x 32 halves = 512 cp16
            int f = tid + i * 256;
            int r = f >> 2, c4 = f & 3;
            bool v = (row0 + r) < M;
            cp16(sA + r * 40 + c4 * 8,
                 A + (size_t)(v ? row0 + r : 0) * kdim + k0 + c4 * 8, v);
        }
        #pragma unroll
        for (int i = 0; i < 2; i++) {                 // B: 32 x 128 halves = 512 cp16
            int f = tid + i * 256;
            int r = f >> 4, c8 = f & 15;
            cp16(sB + r * 136 + c8 * 8,
                 B + (size_t)(k0 + r) * H_DIM + col0 + c8 * 8, true);
        }
    };

    const int warp = tid >> 5;
    const int wm = warp & 3, wn = warp >> 2;

    wmma::fragment<wmma::accumulator, 16, 16, 16, float> acc[2][4];
    #pragma unroll
    for (int i = 0; i < 2; i++)
        #pragma unroll
        for (int j = 0; j < 4; j++) wmma::fill_fragment(acc[i][j], 0.f);

    const int NK = kdim / 32;
    load_tiles(0, 0); CP_COMMIT;

    for (int ks = 0; ks < NK; ks++) {
        if (ks + 1 < NK) { load_tiles((ks + 1) & 1, ks + 1); CP_COMMIT; CP_WAIT1; }
        else             { CP_WAIT0; }
        __syncthreads();

        __half* sA = (__half*)dynraw + (ks & 1) * DN_STG;
        __half* sB = sA + 128 * 40;
        #pragma unroll
        for (int kk = 0; kk < 2; kk++) {
            wmma::fragment<wmma::matrix_a, 16, 16, 16, __half, wmma::row_major> a[2];
            #pragma unroll
            for (int i = 0; i < 2; i++)
                wmma::load_matrix_sync(a[i], sA + (wm * 32 + i * 16) * 40 + kk * 16, 40);
            #pragma unroll
            for (int j = 0; j < 4; j++) {
                wmma::fragment<wmma::matrix_b, 16, 16, 16, __half, wmma::row_major> b;
                wmma::load_matrix_sync(b, sB + (kk * 16) * 136 + wn * 64 + j * 16, 136);
                #pragma unroll
                for (int i = 0; i < 2; i++) wmma::mma_sync(acc[i][j], a[i], b, acc[i][j]);
            }
        }
        __syncthreads();
    }

    // direct global store (weight already folded into activations)
    #pragma unroll
    for (int i = 0; i < 2; i++)
        #pragma unroll
        for (int j = 0; j < 4; j++) {
            float* dst = dstBase + (size_t)(row0 + wm * 32 + i * 16) * H_DIM + col0 + wn * 64 + j * 16;
            wmma::store_matrix_sync(dst, acc[i][j], H_DIM, wmma::mem_row_major);
        }
}

// ---------------- combine: out += sum of 8 routed slots per token ----------------
__global__ void __launch_bounds__(256) combine_kernel(float* __restrict__ out)
{
    int idx = blockIdx.x * 256 + threadIdx.x;            // over T*H/4
    int t = idx >> 9;                                    // H/4 = 512
    int c = idx & 511;
    const int* so = g_slotoff + t * TOPK;
    float4 acc = reinterpret_cast<float4*>(out)[idx];
    #pragma unroll
    for (int r = 0; r < TOPK; r++) {
        float4 v = reinterpret_cast<const float4*>(g_eo + (size_t)so[r] * H_DIM)[c];
        acc.x += v.x; acc.y += v.y; acc.z += v.z; acc.w += v.w;
    }
    reinterpret_cast<float4*>(out)[idx] = acc;
}

// ---------------- launch ----------------
static void launch_f2h(const float* src, void* dstSym, size_t n) {
    size_t n4 = n / 4;
    f2h_kernel<<<(unsigned)((n4 + 255) / 256), 256>>>((const float4*)src, (__half*)dstSym, n4);
}

extern "C" void kernel_launch(void* const* d_in, const int* in_sizes, int n_in,
                              void* d_out, int out_size)
{
    const float* h   = (const float*)d_in[0];
    const float* gw  = (const float*)d_in[1];
    const float* Wg  = (const float*)d_in[2];
    const float* Wu  = (const float*)d_in[3];
    const float* Wd  = (const float*)d_in[4];
    const float* sWg = (const float*)d_in[5];
    const float* sWu = (const float*)d_in[6];
    const float* sWd = (const float*)d_in[7];
    float* out = (float*)d_out;

    void *p_h, *p_wg, *p_wu, *p_wd, *p_swg, *p_swu, *p_swd;
    cudaGetSymbolAddress(&p_h,   hH);
    cudaGetSymbolAddress(&p_wg,  WgH);
    cudaGetSymbolAddress(&p_wu,  WuH);
    cudaGetSymbolAddress(&p_wd,  WdH);
    cudaGetSymbolAddress(&p_swg, sWgH);
    cudaGetSymbolAddress(&p_swu, sWuH);
    cudaGetSymbolAddress(&p_swd, sWdH);

    cudaFuncSetAttribute(gateup_kernel, cudaFuncAttributeMaxDynamicSharedMemorySize, GU_SMEM_BYTES);
    cudaFuncSetAttribute(down_kernel,   cudaFuncAttributeMaxDynamicSharedMemorySize, DN_SMEM_BYTES);

    // fp32 -> fp16 conversions
    launch_f2h(h,   p_h,   (size_t)T_TOK * H_DIM);
    launch_f2h(Wg,  p_wg,  (size_t)NE * H_DIM * IM_DIM);
    launch_f2h(Wu,  p_wu,  (size_t)NE * H_DIM * IM_DIM);
    launch_f2h(Wd,  p_wd,  (size_t)NE * IM_DIM * H_DIM);
    launch_f2h(sWg, p_swg, (size_t)H_DIM * IS_DIM);
    launch_f2h(sWu, p_swu, (size_t)H_DIM * IS_DIM);
    launch_f2h(sWd, p_swd, (size_t)IS_DIM * H_DIM);

    zero_counts_kernel<<<1, 32>>>();
    router_kernel<<<T_TOK / 8, 256>>>(h, gw);

    // merged: z in [0,NE]; z<NE routed expert z, z==NE shared expert
    gateup_kernel<<<dim3(IS_DIM / 64, T_TOK / 128, NE + 1), 256, GU_SMEM_BYTES>>>();
    down_kernel<<<dim3(H_DIM / 128, T_TOK / 128, NE + 1),   256, DN_SMEM_BYTES>>>(out);

    combine_kernel<<<(T_TOK * H_DIM / 4) / 256, 256>>>(out);
}